// round 11
// baseline (speedup 1.0000x reference)
#include <cuda_runtime.h>
#include <cuda_fp16.h>
#include <cstdint>

// Fixed problem shape: N=50000, IN_CH=256, OUT_CH=128, NNZ=800000 per matrix.
#define NNODES 50000
#define FEAT   128
#define IN_CH  256
#define MAXNNZ 800000
#define TOT    (NNODES * FEAT)
#define SLOTS  64                  // per-row bucket capacity (Poisson(16): P(>64) ~ 1e-22)

typedef unsigned long long ull;

// ---------------------------------------------------------------------------
// Static device scratch. m=0 features, m=1 phi_inv, m=2 phi.
// Intermediates in fp16 (halves L2 gather traffic). Cursors are zero on the
// first call (static zero-init) and reset by the SpMM kernels each call.
// ---------------------------------------------------------------------------
__device__ __half g_buf0[TOT];                        // filtered  [N,128] fp16
__device__ __half g_buf1[TOT];                        // tmp       [N,128] fp16
__device__ __half g_wh[IN_CH * FEAT];                 // W in fp16 (64 KB, L1-resident)
__device__ int    g_cursor[3 * NNODES];               // per-row fill cursors == counts
__device__ int2   g_slots[3 * NNODES * SLOTS];        // (col, val-bits) buckets

// ---------------------------------------------------------------------------
// Packed f32x2 helpers (sm_103a): FFMA2 halves the FMA instruction count.
// ---------------------------------------------------------------------------
__device__ __forceinline__ ull fma_f32x2(ull a, ull b, ull c) {
    ull d;
    asm("fma.rn.f32x2 %0, %1, %2, %3;" : "=l"(d) : "l"(a), "l"(b), "l"(c));
    return d;
}
// Convert a half2 (as u32) into a packed f32x2.
__device__ __forceinline__ ull h2_up(unsigned h2) {
    ull r;
    asm("{\n\t"
        ".reg .f16 l, h;\n\t"
        ".reg .f32 fl, fh;\n\t"
        "mov.b32 {l, h}, %1;\n\t"
        "cvt.f32.f16 fl, l;\n\t"
        "cvt.f32.f16 fh, h;\n\t"
        "mov.b64 %0, {fl, fh};\n\t"
        "}" : "=l"(r) : "r"(h2));
    return r;
}
__device__ __forceinline__ ull dupf(float v) {
    ull r; asm("mov.b64 %0, {%1, %1};" : "=l"(r) : "f"(v)); return r;
}
__device__ __forceinline__ float2 unpackf2(ull p) {
    float a, b; asm("mov.b64 {%0, %1}, %2;" : "=f"(a), "=f"(b) : "l"(p));
    return make_float2(a, b);
}

// ---------------------------------------------------------------------------
// Convert W (fp32 [256,128]) to fp16 once per launch. 32768 elements.
// ---------------------------------------------------------------------------
__global__ void convert_w_kernel(const float* __restrict__ W) {
    int i = (blockIdx.x * blockDim.x + threadIdx.x) * 2;
    if (i < IN_CH * FEAT) {
        float2 f = *reinterpret_cast<const float2*>(W + i);
        *reinterpret_cast<__half2*>(g_wh + i) = __floats2half2_rn(f.x, f.y);
    }
}

// ---------------------------------------------------------------------------
// Fused bucket-scatter for all three matrices. blockIdx.y selects the matrix.
// 4 nnz per thread for ILP. theta (matrix 2) folds phi @ diag(theta) in.
// ---------------------------------------------------------------------------
__global__ void scatter_kernel(const int*   __restrict__ rows0, const float* __restrict__ vals0, int nnz0,
                               const int*   __restrict__ rows1, const float* __restrict__ vals1, int nnz1,
                               const int*   __restrict__ rows2, const float* __restrict__ vals2, int nnz2,
                               const float* __restrict__ theta) {
    const int m = blockIdx.y;
    const int* rows; const int* cols; const float* vals; int nnz;
    const float* th = nullptr;
    if (m == 0)      { rows = rows0; cols = rows0 + nnz0; vals = vals0; nnz = nnz0; }
    else if (m == 1) { rows = rows1; cols = rows1 + nnz1; vals = vals1; nnz = nnz1; }
    else             { rows = rows2; cols = rows2 + nnz2; vals = vals2; nnz = nnz2; th = theta; }

    int base = (blockIdx.x * blockDim.x + threadIdx.x) * 4;
    if (base >= nnz) return;

    int*  cur   = g_cursor + m * NNODES;
    int2* slots = g_slots + (unsigned)m * (unsigned)(NNODES * SLOTS);

    if (base + 4 <= nnz) {
        int4   r4 = *reinterpret_cast<const int4*>(rows + base);
        int4   c4 = *reinterpret_cast<const int4*>(cols + base);
        float4 v4 = *reinterpret_cast<const float4*>(vals + base);
        int   r[4] = {r4.x, r4.y, r4.z, r4.w};
        int   c[4] = {c4.x, c4.y, c4.z, c4.w};
        float v[4] = {v4.x, v4.y, v4.z, v4.w};
        #pragma unroll
        for (int k = 0; k < 4; k++) {
            float vv = v[k];
            if (th) vv *= __ldg(th + c[k]);
            int pos = atomicAdd(cur + r[k], 1);
            slots[(unsigned)r[k] * SLOTS + (unsigned)pos] = make_int2(c[k], __float_as_int(vv));
        }
    } else {
        for (int i = base; i < nnz && i < base + 4; i++) {
            int r = __ldg(rows + i);
            int c = __ldg(cols + i);
            float vv = __ldg(vals + i);
            if (th) vv *= __ldg(th + c);
            int pos = atomicAdd(cur + r, 1);
            slots[(unsigned)r * SLOTS + (unsigned)pos] = make_int2(c, __float_as_int(vv));
        }
    }
}

// ---------------------------------------------------------------------------
// Gather SpMM: out[row,:] = sum_j val_j * dense[col_j, :]   (F = 128)
// One warp per row. Entries read via broadcast LDG.64 (all lanes same addr,
// 1 wavefront, L1-resident) -- no shuffles. Inner math uses packed FFMA2.
// 4 independent row loads in flight per batch. Cursor reset for next call.
// Accumulation fp32 (f32x2 lanes); fp16 in/out storage per template flags.
// ---------------------------------------------------------------------------
template <bool OUT_HALF, bool RELU>
__global__ void spmm_gather_kernel(int m,
                                   const __half* __restrict__ dense,
                                   void*         __restrict__ out_v) {
    int row  = (blockIdx.x * blockDim.x + threadIdx.x) >> 5;
    int lane = threadIdx.x & 31;
    if (row >= NNODES) return;

    const int cidx = m * NNODES + row;
    int cnt = __ldg(g_cursor + cidx);
    if (lane == 0) g_cursor[cidx] = 0;       // reset for the next execution
    if (cnt > SLOTS) cnt = SLOTS;

    const int2* e = g_slots + (unsigned)m * (unsigned)(NNODES * SLOTS)
                           + (unsigned)row * SLOTS;

    // Packed f32x2 accumulators: a = features [4l+0,4l+1], b = [4l+2,4l+3].
    // Two sets to break the FFMA2 dependency chain.
    ull a0 = 0ull, b0 = 0ull, a1 = 0ull, b1 = 0ull;

    int i = 0;
    for (; i + 4 <= cnt; i += 4) {
        int2 e0 = __ldg(e + i);
        int2 e1 = __ldg(e + i + 1);
        int2 e2 = __ldg(e + i + 2);
        int2 e3 = __ldg(e + i + 3);
        ull v0 = dupf(__int_as_float(e0.y));
        ull v1 = dupf(__int_as_float(e1.y));
        ull v2 = dupf(__int_as_float(e2.y));
        ull v3 = dupf(__int_as_float(e3.y));
        uint2 r0 = __ldg(reinterpret_cast<const uint2*>(dense + (unsigned)e0.x * FEAT) + lane);
        uint2 r1 = __ldg(reinterpret_cast<const uint2*>(dense + (unsigned)e1.x * FEAT) + lane);
        uint2 r2 = __ldg(reinterpret_cast<const uint2*>(dense + (unsigned)e2.x * FEAT) + lane);
        uint2 r3 = __ldg(reinterpret_cast<const uint2*>(dense + (unsigned)e3.x * FEAT) + lane);
        a0 = fma_f32x2(h2_up(r0.x), v0, a0);  b0 = fma_f32x2(h2_up(r0.y), v0, b0);
        a1 = fma_f32x2(h2_up(r1.x), v1, a1);  b1 = fma_f32x2(h2_up(r1.y), v1, b1);
        a0 = fma_f32x2(h2_up(r2.x), v2, a0);  b0 = fma_f32x2(h2_up(r2.y), v2, b0);
        a1 = fma_f32x2(h2_up(r3.x), v3, a1);  b1 = fma_f32x2(h2_up(r3.y), v3, b1);
    }
    for (; i < cnt; i++) {
        int2 e0 = __ldg(e + i);
        ull v0 = dupf(__int_as_float(e0.y));
        uint2 r0 = __ldg(reinterpret_cast<const uint2*>(dense + (unsigned)e0.x * FEAT) + lane);
        a0 = fma_f32x2(h2_up(r0.x), v0, a0);  b0 = fma_f32x2(h2_up(r0.y), v0, b0);
    }

    float2 fa0 = unpackf2(a0), fa1 = unpackf2(a1);
    float2 fb0 = unpackf2(b0), fb1 = unpackf2(b1);
    float4 r;
    r.x = fa0.x + fa1.x;
    r.y = fa0.y + fa1.y;
    r.z = fb0.x + fb1.x;
    r.w = fb0.y + fb1.y;
    if (RELU) {
        r.x = fmaxf(r.x, 0.f); r.y = fmaxf(r.y, 0.f);
        r.z = fmaxf(r.z, 0.f); r.w = fmaxf(r.w, 0.f);
    }

    if (OUT_HALF) {
        __half2 h0 = __floats2half2_rn(r.x, r.y);
        __half2 h1 = __floats2half2_rn(r.z, r.w);
        uint2 packed;
        packed.x = *reinterpret_cast<unsigned*>(&h0);
        packed.y = *reinterpret_cast<unsigned*>(&h1);
        reinterpret_cast<uint2*>((__half*)out_v + (unsigned)row * FEAT)[lane] = packed;
    } else {
        reinterpret_cast<float4*>((float*)out_v + (unsigned)row * FEAT)[lane] = r;
    }
}

// ---------------------------------------------------------------------------
// Launch sequence (graph-capturable, 5 kernels).
// Inputs:
//   0 phi_indices int32[2,NNZ]  1 phi_values f32[NNZ]
//   2 phi_inv_indices           3 phi_inv_values
//   4 feature_indices           5 feature_values
//   6 weight_matrix f32[256,128] 7 theta f32[N]  8 dropout (ignored)
// ---------------------------------------------------------------------------
extern "C" void kernel_launch(void* const* d_in, const int* in_sizes, int n_in,
                              void* d_out, int out_size) {
    const int*   phi_idx    = (const int*)  d_in[0];
    const float* phi_vals   = (const float*)d_in[1];
    const int*   phinv_idx  = (const int*)  d_in[2];
    const float* phinv_vals = (const float*)d_in[3];
    const int*   feat_idx   = (const int*)  d_in[4];
    const float* feat_vals  = (const float*)d_in[5];
    const float* W          = (const float*)d_in[6];
    const float* theta      = (const float*)d_in[7];
    float*       out        = (float*)d_out;

    const int nnz_phi   = in_sizes[1];
    const int nnz_phinv = in_sizes[3];
    const int nnz_feat  = in_sizes[5];

    __half* buf0 = nullptr; __half* buf1 = nullptr; __half* wh = nullptr;
    cudaGetSymbolAddress((void**)&buf0, g_buf0);
    cudaGetSymbolAddress((void**)&buf1, g_buf1);
    cudaGetSymbolAddress((void**)&wh,   g_wh);

    const int B = 256;

    // 1) W -> fp16 (tiny)
    convert_w_kernel<<<(IN_CH * FEAT / 2 + B - 1) / B, B>>>(W);

    // 2) fused bucket scatter for all three matrices
    //    (cursors zero: static init on first call, reset by SpMMs afterwards)
    int nnz_max = nnz_feat;
    if (nnz_phinv > nnz_max) nnz_max = nnz_phinv;
    if (nnz_phi   > nnz_max) nnz_max = nnz_phi;
    dim3 sgrid((nnz_max + 4 * B - 1) / (4 * B), 3);
    scatter_kernel<<<sgrid, B>>>(feat_idx,  feat_vals,  nnz_feat,
                                 phinv_idx, phinv_vals, nnz_phinv,
                                 phi_idx,   phi_vals,   nnz_phi,
                                 theta);

    // 3) three gather SpMMs: f16 W -> f16 buf0 -> f16 buf1 -> f32 out (+ReLU)
    const int SG = (NNODES * 32 + B - 1) / B;    // warp per row
    spmm_gather_kernel<true,  false><<<SG, B>>>(0, wh,   buf0);
    spmm_gather_kernel<true,  false><<<SG, B>>>(1, buf0, buf1);
    spmm_gather_kernel<false, true ><<<SG, B>>>(2, buf1, out);
}

// round 12
// speedup vs baseline: 2.4555x; 2.4555x over previous
#include <cuda_runtime.h>
#include <cuda_fp16.h>
#include <cstdint>

// Fixed problem shape: N=50000, IN_CH=256, OUT_CH=128, NNZ=800000 per matrix.
#define NNODES 50000
#define FEAT   128
#define IN_CH  256
#define MAXNNZ 800000
#define TOT    (NNODES * FEAT)
#define SLOTS  64                  // per-row bucket capacity (Poisson(16): P(>64) ~ 1e-22)
#define FULLM  0xFFFFFFFFu

// ---------------------------------------------------------------------------
// Static device scratch. m=0 features, m=1 phi_inv, m=2 phi.
// Intermediates in fp16 (halves L2 gather traffic vs fp32). Cursors are zero
// on first call (static zero-init) and reset in-kernel for the next replay.
// ---------------------------------------------------------------------------
__device__ __half g_buf0[TOT];                        // filtered  [N,128] fp16
__device__ __half g_buf1[TOT];                        // tmp       [N,128] fp16
__device__ __half g_wh[IN_CH * FEAT];                 // W in fp16 (64 KB, L1-resident)
__device__ int    g_cursor[3 * NNODES];               // per-row fill cursors == counts
__device__ int2   g_slots[3 * NNODES * SLOTS];        // (col, val-bits) buckets

// ---------------------------------------------------------------------------
// Convert W (fp32 [256,128]) to fp16 once per launch. 32768 elements.
// ---------------------------------------------------------------------------
__global__ void convert_w_kernel(const float* __restrict__ W) {
    int i = (blockIdx.x * blockDim.x + threadIdx.x) * 2;
    if (i < IN_CH * FEAT) {
        float2 f = *reinterpret_cast<const float2*>(W + i);
        *reinterpret_cast<__half2*>(g_wh + i) = __floats2half2_rn(f.x, f.y);
    }
}

// ---------------------------------------------------------------------------
// Fused bucket-scatter for all three matrices. blockIdx.y selects the matrix.
// 4 nnz per thread for ILP. theta (matrix 2) folds phi @ diag(theta) in.
// ---------------------------------------------------------------------------
__global__ void scatter_kernel(const int*   __restrict__ rows0, const float* __restrict__ vals0, int nnz0,
                               const int*   __restrict__ rows1, const float* __restrict__ vals1, int nnz1,
                               const int*   __restrict__ rows2, const float* __restrict__ vals2, int nnz2,
                               const float* __restrict__ theta) {
    const int m = blockIdx.y;
    const int* rows; const int* cols; const float* vals; int nnz;
    const float* th = nullptr;
    if (m == 0)      { rows = rows0; cols = rows0 + nnz0; vals = vals0; nnz = nnz0; }
    else if (m == 1) { rows = rows1; cols = rows1 + nnz1; vals = vals1; nnz = nnz1; }
    else             { rows = rows2; cols = rows2 + nnz2; vals = vals2; nnz = nnz2; th = theta; }

    int base = (blockIdx.x * blockDim.x + threadIdx.x) * 4;
    if (base >= nnz) return;

    int*  cur   = g_cursor + m * NNODES;
    int2* slots = g_slots + (unsigned)m * (unsigned)(NNODES * SLOTS);

    if (base + 4 <= nnz) {
        int4   r4 = *reinterpret_cast<const int4*>(rows + base);
        int4   c4 = *reinterpret_cast<const int4*>(cols + base);
        float4 v4 = *reinterpret_cast<const float4*>(vals + base);
        int   r[4] = {r4.x, r4.y, r4.z, r4.w};
        int   c[4] = {c4.x, c4.y, c4.z, c4.w};
        float v[4] = {v4.x, v4.y, v4.z, v4.w};
        #pragma unroll
        for (int k = 0; k < 4; k++) {
            float vv = v[k];
            if (th) vv *= __ldg(th + c[k]);
            int pos = atomicAdd(cur + r[k], 1);
            slots[(unsigned)r[k] * SLOTS + (unsigned)pos] = make_int2(c[k], __float_as_int(vv));
        }
    } else {
        for (int i = base; i < nnz && i < base + 4; i++) {
            int r = __ldg(rows + i);
            int c = __ldg(cols + i);
            float vv = __ldg(vals + i);
            if (th) vv *= __ldg(th + c);
            int pos = atomicAdd(cur + r, 1);
            slots[(unsigned)r * SLOTS + (unsigned)pos] = make_int2(c, __float_as_int(vv));
        }
    }
}

// ---------------------------------------------------------------------------
// fp16 row load: lane loads uint2 (4 halves, 8 B) -> warp covers 256 B.
// ---------------------------------------------------------------------------
__device__ __forceinline__ float4 load_row_f16(const __half* base, unsigned c, int lane) {
    uint2 raw = __ldg(reinterpret_cast<const uint2*>(base + c * FEAT) + lane);
    __half2 h0 = *reinterpret_cast<__half2*>(&raw.x);
    __half2 h1 = *reinterpret_cast<__half2*>(&raw.y);
    float2 f0 = __half22float2(h0);
    float2 f1 = __half22float2(h1);
    return make_float4(f0.x, f0.y, f1.x, f1.y);
}

// ---------------------------------------------------------------------------
// Gather SpMM (round-9 proven structure): out[row,:] = sum_j v_j * dense[c_j,:]
// One warp per row. Lane i prefetches entry i with ONE coalesced 8B load;
// cols/vals broadcast via shfl (register-resident) so the 4 dense loads per
// batch are fully independent. fp32 accumulation. Cursor reset in-kernel.
// ---------------------------------------------------------------------------
template <bool OUT_HALF, bool RELU>
__global__ void spmm_gather_kernel(int m,
                                   const __half* __restrict__ dense,
                                   void*         __restrict__ out_v) {
    int row  = (blockIdx.x * blockDim.x + threadIdx.x) >> 5;
    int lane = threadIdx.x & 31;
    if (row >= NNODES) return;

    const int cidx = m * NNODES + row;
    int cnt = __ldg(g_cursor + cidx);
    if (lane == 0) g_cursor[cidx] = 0;       // reset for the next execution
    if (cnt > SLOTS) cnt = SLOTS;

    const int2* e = g_slots + (unsigned)m * (unsigned)(NNODES * SLOTS)
                           + (unsigned)row * SLOTS;

    // One coalesced load covers entries 0..31 for the whole warp.
    int2 my_e = make_int2(0, 0);
    if (lane < cnt) my_e = __ldg(e + lane);

    float4 acc0 = make_float4(0.f, 0.f, 0.f, 0.f);
    float4 acc1 = make_float4(0.f, 0.f, 0.f, 0.f);

    const int n32 = (cnt < 32) ? cnt : 32;
    int i = 0;
    for (; i + 4 <= n32; i += 4) {
        unsigned c0 = (unsigned)__shfl_sync(FULLM, my_e.x, i);
        unsigned c1 = (unsigned)__shfl_sync(FULLM, my_e.x, i + 1);
        unsigned c2 = (unsigned)__shfl_sync(FULLM, my_e.x, i + 2);
        unsigned c3 = (unsigned)__shfl_sync(FULLM, my_e.x, i + 3);
        float v0 = __int_as_float(__shfl_sync(FULLM, my_e.y, i));
        float v1 = __int_as_float(__shfl_sync(FULLM, my_e.y, i + 1));
        float v2 = __int_as_float(__shfl_sync(FULLM, my_e.y, i + 2));
        float v3 = __int_as_float(__shfl_sync(FULLM, my_e.y, i + 3));
        // 4 independent loads in flight
        float4 x0 = load_row_f16(dense, c0, lane);
        float4 x1 = load_row_f16(dense, c1, lane);
        float4 x2 = load_row_f16(dense, c2, lane);
        float4 x3 = load_row_f16(dense, c3, lane);
        acc0.x += v0 * x0.x; acc0.y += v0 * x0.y; acc0.z += v0 * x0.z; acc0.w += v0 * x0.w;
        acc1.x += v1 * x1.x; acc1.y += v1 * x1.y; acc1.z += v1 * x1.z; acc1.w += v1 * x1.w;
        acc0.x += v2 * x2.x; acc0.y += v2 * x2.y; acc0.z += v2 * x2.z; acc0.w += v2 * x2.w;
        acc1.x += v3 * x3.x; acc1.y += v3 * x3.y; acc1.z += v3 * x3.z; acc1.w += v3 * x3.w;
    }
    for (; i < n32; i++) {
        unsigned c0 = (unsigned)__shfl_sync(FULLM, my_e.x, i);
        float    v0 = __int_as_float(__shfl_sync(FULLM, my_e.y, i));
        float4 x0 = load_row_f16(dense, c0, lane);
        acc0.x += v0 * x0.x; acc0.y += v0 * x0.y; acc0.z += v0 * x0.z; acc0.w += v0 * x0.w;
    }
    // Rare tail: rows with more than 32 entries (~1e-4 of rows).
    for (; i < cnt; i++) {
        int2 ee = __ldg(e + i);
        float vv = __int_as_float(ee.y);
        float4 x0 = load_row_f16(dense, (unsigned)ee.x, lane);
        acc0.x += vv * x0.x; acc0.y += vv * x0.y; acc0.z += vv * x0.z; acc0.w += vv * x0.w;
    }

    float4 r;
    r.x = acc0.x + acc1.x;
    r.y = acc0.y + acc1.y;
    r.z = acc0.z + acc1.z;
    r.w = acc0.w + acc1.w;
    if (RELU) {
        r.x = fmaxf(r.x, 0.f); r.y = fmaxf(r.y, 0.f);
        r.z = fmaxf(r.z, 0.f); r.w = fmaxf(r.w, 0.f);
    }

    if (OUT_HALF) {
        __half2 h0 = __floats2half2_rn(r.x, r.y);
        __half2 h1 = __floats2half2_rn(r.z, r.w);
        uint2 packed;
        packed.x = *reinterpret_cast<unsigned*>(&h0);
        packed.y = *reinterpret_cast<unsigned*>(&h1);
        reinterpret_cast<uint2*>((__half*)out_v + (unsigned)row * FEAT)[lane] = packed;
    } else {
        reinterpret_cast<float4*>((float*)out_v + (unsigned)row * FEAT)[lane] = r;
    }
}

// ---------------------------------------------------------------------------
// Launch sequence (graph-capturable, 5 kernels).
// Inputs:
//   0 phi_indices int32[2,NNZ]  1 phi_values f32[NNZ]
//   2 phi_inv_indices           3 phi_inv_values
//   4 feature_indices           5 feature_values
//   6 weight_matrix f32[256,128] 7 theta f32[N]  8 dropout (ignored)
// ---------------------------------------------------------------------------
extern "C" void kernel_launch(void* const* d_in, const int* in_sizes, int n_in,
                              void* d_out, int out_size) {
    const int*   phi_idx    = (const int*)  d_in[0];
    const float* phi_vals   = (const float*)d_in[1];
    const int*   phinv_idx  = (const int*)  d_in[2];
    const float* phinv_vals = (const float*)d_in[3];
    const int*   feat_idx   = (const int*)  d_in[4];
    const float* feat_vals  = (const float*)d_in[5];
    const float* W          = (const float*)d_in[6];
    const float* theta      = (const float*)d_in[7];
    float*       out        = (float*)d_out;

    const int nnz_phi   = in_sizes[1];
    const int nnz_phinv = in_sizes[3];
    const int nnz_feat  = in_sizes[5];

    __half* buf0 = nullptr; __half* buf1 = nullptr; __half* wh = nullptr;
    cudaGetSymbolAddress((void**)&buf0, g_buf0);
    cudaGetSymbolAddress((void**)&buf1, g_buf1);
    cudaGetSymbolAddress((void**)&wh,   g_wh);

    const int B = 256;

    // 1) W -> fp16 (tiny)
    convert_w_kernel<<<(IN_CH * FEAT / 2 + B - 1) / B, B>>>(W);

    // 2) fused bucket scatter for all three matrices
    //    (cursors zero: static init on first call, reset by SpMMs afterwards)
    int nnz_max = nnz_feat;
    if (nnz_phinv > nnz_max) nnz_max = nnz_phinv;
    if (nnz_phi   > nnz_max) nnz_max = nnz_phi;
    dim3 sgrid((nnz_max + 4 * B - 1) / (4 * B), 3);
    scatter_kernel<<<sgrid, B>>>(feat_idx,  feat_vals,  nnz_feat,
                                 phinv_idx, phinv_vals, nnz_phinv,
                                 phi_idx,   phi_vals,   nnz_phi,
                                 theta);

    // 3) three gather SpMMs: f16 W -> f16 buf0 -> f16 buf1 -> f32 out (+ReLU)
    const int SG = (NNODES * 32 + B - 1) / B;    // warp per row
    spmm_gather_kernel<true,  false><<<SG, B>>>(0, wh,   buf0);
    spmm_gather_kernel<true,  false><<<SG, B>>>(1, buf0, buf1);
    spmm_gather_kernel<false, true ><<<SG, B>>>(2, buf1, out);
}